// round 3
// baseline (speedup 1.0000x reference)
#include <cuda_runtime.h>
#include <cuda.h>
#include <cstdint>

// ============================================================================
// Problem constants
// ============================================================================
#define M_DIM 8192
#define N_DIM 4096
#define K_DIM 4096
#define BM 128
#define BN 256
#define BK 128
#define STAGES 4
#define NTHREADS 256
#define KIT (K_DIM / BK)  // 32

// Stage = A tile [128 rows][128 B] + B tile [256 rows][128 B]
#define A_TILE_BYTES (BM * BK)                      // 16384
#define B_TILE_BYTES (BN * BK)                      // 32768
#define STAGE_BYTES  (A_TILE_BYTES + B_TILE_BYTES)  // 49152
#define SOFF_FULL 0
#define SOFF_TILE 1024
#define SMEM_TOTAL (SOFF_TILE + STAGES * STAGE_BYTES)  // 197632

// fp8 scratch (device globals: allocation-free contract)
__device__ __align__(1024) unsigned char g_qx[(size_t)M_DIM * K_DIM];
__device__ __align__(1024) unsigned char g_qw[(size_t)N_DIM * K_DIM];

// ============================================================================
// PTX helpers (baseline sm_90/sm_89 features only — NO tcgen05)
// ============================================================================
__device__ __forceinline__ uint32_t smem_u32(const void* p) {
    uint32_t a;
    asm("{ .reg .u64 t; cvta.to.shared.u64 t, %1; cvt.u32.u64 %0, t; }"
        : "=r"(a) : "l"(p));
    return a;
}

#define MBARRIER_INIT(addr, count) \
    asm volatile("mbarrier.init.shared.b64 [%0], %1;" \
                 :: "r"((uint32_t)(addr)), "r"((uint32_t)(count)) : "memory")

#define MBARRIER_EXPECT_TX(addr, bytes) \
    asm volatile("mbarrier.arrive.expect_tx.shared.b64 _, [%0], %1;" \
                 :: "r"((uint32_t)(addr)), "r"((uint32_t)(bytes)) : "memory")

#define MBARRIER_WAIT_PARITY(addr, parity) do { \
    uint32_t _m = (uint32_t)(addr); uint32_t _p = (uint32_t)(parity); uint32_t _d; \
    asm volatile("{\n\t.reg .pred p;\n\t" \
        "mbarrier.try_wait.parity.acquire.cta.shared::cta.b64 p, [%1], %2;\n\t" \
        "selp.b32 %0, 1, 0, p;\n\t}" : "=r"(_d) : "r"(_m), "r"(_p) : "memory"); \
    if (!_d) { \
        asm volatile("{\n\t.reg .pred P1;\n\t" \
            "WL_%=:\n\t" \
            "mbarrier.try_wait.parity.acquire.cta.shared::cta.b64 P1, [%0], %1, 0x989680;\n\t" \
            "@P1 bra.uni WD_%=;\n\t" \
            "bra.uni WL_%=;\n\t" \
            "WD_%=:\n\t}" :: "r"(_m), "r"(_p) : "memory"); \
    } \
} while (0)

#define TMA_LOAD_2D(smem_addr, tmap_ptr, cx, cy, mbar) \
    asm volatile( \
        "cp.async.bulk.tensor.2d.shared::cta.global.tile.mbarrier::complete_tx::bytes " \
        "[%0], [%1, {%2, %3}], [%4];" \
        :: "r"((uint32_t)(smem_addr)), "l"(tmap_ptr), \
           "r"((int32_t)(cx)), "r"((int32_t)(cy)), "r"((uint32_t)(mbar)) : "memory")

__device__ __forceinline__ uint32_t lds32(uint32_t a) {
    uint32_t v;
    asm volatile("ld.shared.b32 %0, [%1];" : "=r"(v) : "r"(a));
    return v;
}

// fp8 e4m3 x e4m3 -> f32 mma, in-place accumulate (sm_89+ baseline feature)
__device__ __forceinline__ void mma_e4m3(float* d, const uint32_t* a,
                                         const uint32_t* b) {
    asm volatile(
        "mma.sync.aligned.m16n8k32.row.col.f32.e4m3.e4m3.f32 "
        "{%0,%1,%2,%3}, {%4,%5,%6,%7}, {%8,%9}, {%0,%1,%2,%3};"
        : "+f"(d[0]), "+f"(d[1]), "+f"(d[2]), "+f"(d[3])
        : "r"(a[0]), "r"(a[1]), "r"(a[2]), "r"(a[3]), "r"(b[0]), "r"(b[1]));
}

// ============================================================================
// Kernel 1: fp32 -> fp8 e4m3 quantization (matches reference path: IEEE div
// by scale, saturating rn cast to e4m3 grid). Weight path: scale=1 (values
// already on the e4m3 grid; rn cast is exact). 4 independent loads per
// thread for MLP.
// ============================================================================
__global__ void quant_kernel(const float4* __restrict__ src,
                             uint32_t* __restrict__ dst,
                             int n4,
                             const float* __restrict__ scale) {
    const float s = scale ? __ldg(scale) : 1.0f;
    const int base = blockIdx.x * blockDim.x + threadIdx.x;
    const int stride = gridDim.x * blockDim.x;
    #pragma unroll
    for (int j = 0; j < 4; j++) {
        int i = base + j * stride;
        if (i >= n4) break;
        float4 v = src[i];
        float a = __fdiv_rn(v.x, s);
        float b = __fdiv_rn(v.y, s);
        float c = __fdiv_rn(v.z, s);
        float d = __fdiv_rn(v.w, s);
        uint16_t lo, hi;
        // cvt d, a, b: d[7:0]=cvt(b), d[15:8]=cvt(a) -> byte0 = element 0
        asm("cvt.rn.satfinite.e4m3x2.f32 %0, %1, %2;" : "=h"(lo) : "f"(b), "f"(a));
        asm("cvt.rn.satfinite.e4m3x2.f32 %0, %1, %2;" : "=h"(hi) : "f"(d), "f"(c));
        dst[i] = (uint32_t)lo | ((uint32_t)hi << 16);
    }
}

// ============================================================================
// Kernel 2: multistage fp8 mma.sync GEMM
//   out[128,256] tile = qx[128,K] @ qw[256,K]^T  (both K-major)
//   8 warps (2 M x 4 N), warp tile 64x64; 4-stage TMA pipeline; SW128
// ============================================================================
__device__ __forceinline__ void issue_stage(uint32_t sbase, int it, int m0,
                                            int n0, const CUtensorMap* tA,
                                            const CUtensorMap* tB) {
    int s = it % STAGES;
    uint32_t full = sbase + SOFF_FULL + 8 * s;
    MBARRIER_EXPECT_TX(full, STAGE_BYTES);
    uint32_t st = sbase + SOFF_TILE + s * STAGE_BYTES;
    int k0 = it * BK;
    TMA_LOAD_2D(st,                tA, k0, m0, full);
    TMA_LOAD_2D(st + A_TILE_BYTES, tB, k0, n0, full);
}

__global__ void __launch_bounds__(NTHREADS, 1)
fp8_gemm_kernel(const __grid_constant__ CUtensorMap tmA,
                const __grid_constant__ CUtensorMap tmB,
                const float* __restrict__ bias,
                const float* __restrict__ in_scale,
                const float* __restrict__ w_scale,
                float* __restrict__ out) {
    extern __shared__ __align__(1024) unsigned char smem[];
    const uint32_t sbase = smem_u32(smem);
    const int tid = threadIdx.x;
    const int wid = tid >> 5;
    const int lane = tid & 31;
    const int gid = lane >> 2;   // group id 0..7 (fragment row-in-8)
    const int tig = lane & 3;    // thread-in-group
    const int warp_m = (wid & 1) * 64;    // 2 warps along M
    const int warp_n = (wid >> 1) * 64;   // 4 warps along N
    const int m0 = blockIdx.y * BM;
    const int n0 = blockIdx.x * BN;

    if (tid == 0) {
        #pragma unroll
        for (int s = 0; s < STAGES; s++)
            MBARRIER_INIT(sbase + SOFF_FULL + 8 * s, 1);
    }
    __syncthreads();

    // Prologue: fill STAGES-1 stages
    if (tid == 0) {
        issue_stage(sbase, 0, m0, n0, &tmA, &tmB);
        issue_stage(sbase, 1, m0, n0, &tmA, &tmB);
        issue_stage(sbase, 2, m0, n0, &tmA, &tmB);
    }

    // SW128 swizzle term for our rows is ((row&7)<<4) = gid<<4, constant
    // per thread. co[s4][h] = (s4*32 + h*16 + tig*4) ^ (gid<<4).
    const uint32_t sx = (uint32_t)gid << 4;
    uint32_t co[4][2];
    #pragma unroll
    for (int s4 = 0; s4 < 4; s4++) {
        #pragma unroll
        for (int h = 0; h < 2; h++)
            co[s4][h] = ((uint32_t)(s4 * 32 + h * 16 + tig * 4)) ^ sx;
    }
    const uint32_t baseA0 = (uint32_t)(warp_m + gid) * 128;
    const uint32_t baseB0 = (uint32_t)(warp_n + gid) * 128 + A_TILE_BYTES;

    float acc[4][8][4];   // 128 f32 accumulators, direct mma accumulation
    #pragma unroll
    for (int i = 0; i < 4; i++)
        #pragma unroll
        for (int j = 0; j < 8; j++)
            #pragma unroll
            for (int q = 0; q < 4; q++) acc[i][j][q] = 0.f;

    int s = 0, ph = 0;
    for (int it = 0; it < KIT; ++it) {
        MBARRIER_WAIT_PARITY(sbase + SOFF_FULL + 8 * s, ph);
        if (tid == 0 && it + 3 < KIT)
            issue_stage(sbase, it + 3, m0, n0, &tmA, &tmB);

        const uint32_t stg = sbase + SOFF_TILE + (uint32_t)s * STAGE_BYTES;
        const uint32_t aBase = stg + baseA0;
        const uint32_t bBase = stg + baseB0;
        #pragma unroll
        for (int s4 = 0; s4 < 4; s4++) {  // 4 x K=32 per BK=128 stage
            uint32_t Af[4][4];
            #pragma unroll
            for (int fm = 0; fm < 4; fm++) {
                const uint32_t a0 = aBase + fm * 2048 + co[s4][0];
                const uint32_t a1 = aBase + fm * 2048 + co[s4][1];
                Af[fm][0] = lds32(a0);
                Af[fm][1] = lds32(a0 + 1024);
                Af[fm][2] = lds32(a1);
                Af[fm][3] = lds32(a1 + 1024);
            }
            #pragma unroll
            for (int fn = 0; fn < 8; fn++) {  // B liveness kept to 2 regs
                const uint32_t b0 = bBase + fn * 1024;
                uint32_t Bf[2];
                Bf[0] = lds32(b0 + co[s4][0]);
                Bf[1] = lds32(b0 + co[s4][1]);
                #pragma unroll
                for (int fm = 0; fm < 4; fm++)
                    mma_e4m3(acc[fm][fn], Af[fm], Bf);
            }
        }
        __syncthreads();  // all reads of stage s done; buffer reusable
        if (++s == STAGES) { s = 0; ph ^= 1; }
    }

    // Epilogue: scale + bias, float2 stores
    const float sc = __ldg(in_scale) * __ldg(w_scale);
    #pragma unroll
    for (int fm = 0; fm < 4; fm++) {
        const int r0 = m0 + warp_m + fm * 16 + gid;
        #pragma unroll
        for (int fn = 0; fn < 8; fn++) {
            const int col = n0 + warp_n + fn * 8 + 2 * tig;
            const float2 bv = *reinterpret_cast<const float2*>(bias + col);
            float2 o0, o1;
            o0.x = fmaf(acc[fm][fn][0], sc, bv.x);
            o0.y = fmaf(acc[fm][fn][1], sc, bv.y);
            o1.x = fmaf(acc[fm][fn][2], sc, bv.x);
            o1.y = fmaf(acc[fm][fn][3], sc, bv.y);
            *reinterpret_cast<float2*>(out + (size_t)r0 * N_DIM + col) = o0;
            *reinterpret_cast<float2*>(out + (size_t)(r0 + 8) * N_DIM + col) = o1;
        }
    }
}

// ============================================================================
// Host launch
// ============================================================================
typedef CUresult (CUDAAPI* PFN_encodeTiled)(
    CUtensorMap*, CUtensorMapDataType, cuuint32_t, void*,
    const cuuint64_t*, const cuuint64_t*, const cuuint32_t*, const cuuint32_t*,
    CUtensorMapInterleave, CUtensorMapSwizzle, CUtensorMapL2promotion,
    CUtensorMapFloatOOBfill);

extern "C" void kernel_launch(void* const* d_in, const int* in_sizes, int n_in,
                              void* d_out, int out_size) {
    const float* x      = (const float*)d_in[0];
    const float* w      = (const float*)d_in[1];
    const float* wscale = (const float*)d_in[2];
    const float* bias   = (const float*)d_in[3];
    const float* iscale = (const float*)d_in[4];
    float* out = (float*)d_out;
    (void)in_sizes; (void)n_in; (void)out_size;

    void* qx_p = nullptr; void* qw_p = nullptr;
    cudaGetSymbolAddress(&qx_p, g_qx);
    cudaGetSymbolAddress(&qw_p, g_qw);

    // --- quantize activations (/input_scale) and weights (exact re-cast) ---
    int n4x = M_DIM * K_DIM / 4;   // 8388608
    int n4w = N_DIM * K_DIM / 4;   // 4194304
    quant_kernel<<<n4x / (256 * 4), 256>>>(
        (const float4*)x, (uint32_t*)qx_p, n4x, iscale);
    quant_kernel<<<n4w / (256 * 4), 256>>>(
        (const float4*)w, (uint32_t*)qw_p, n4w, nullptr);

    // --- TMA descriptors (driver entry point via cudart; no -lcuda needed) ---
    PFN_encodeTiled encode = nullptr;
    cudaDriverEntryPointQueryResult qr;
    cudaGetDriverEntryPoint("cuTensorMapEncodeTiled", (void**)&encode,
                            cudaEnableDefault, &qr);

    CUtensorMap tmA, tmB;
    {
        cuuint64_t dims[2]    = {K_DIM, M_DIM};
        cuuint64_t strides[1] = {K_DIM};   // bytes (uint8 elems)
        cuuint32_t box[2]     = {BK, BM};  // 128B rows: SW128 limit
        cuuint32_t es[2]      = {1, 1};
        encode(&tmA, CU_TENSOR_MAP_DATA_TYPE_UINT8, 2, qx_p, dims, strides,
               box, es, CU_TENSOR_MAP_INTERLEAVE_NONE, CU_TENSOR_MAP_SWIZZLE_128B,
               CU_TENSOR_MAP_L2_PROMOTION_L2_128B, CU_TENSOR_MAP_FLOAT_OOB_FILL_NONE);
    }
    {
        cuuint64_t dims[2]    = {K_DIM, N_DIM};
        cuuint64_t strides[1] = {K_DIM};
        cuuint32_t box[2]     = {BK, BN};  // 128 x 256 box (dim max 256: ok)
        cuuint32_t es[2]      = {1, 1};
        encode(&tmB, CU_TENSOR_MAP_DATA_TYPE_UINT8, 2, qw_p, dims, strides,
               box, es, CU_TENSOR_MAP_INTERLEAVE_NONE, CU_TENSOR_MAP_SWIZZLE_128B,
               CU_TENSOR_MAP_L2_PROMOTION_L2_128B, CU_TENSOR_MAP_FLOAT_OOB_FILL_NONE);
    }

    cudaFuncSetAttribute(fp8_gemm_kernel,
                         cudaFuncAttributeMaxDynamicSharedMemorySize, SMEM_TOTAL);
    dim3 grid(N_DIM / BN, M_DIM / BM);  // (16, 64) = 1024 CTAs
    fp8_gemm_kernel<<<grid, NTHREADS, SMEM_TOTAL>>>(
        tmA, tmB, bias, iscale, wscale, out);
}

// round 4
// speedup vs baseline: 1.0367x; 1.0367x over previous
#include <cuda_runtime.h>
#include <cuda.h>
#include <cstdint>

// ============================================================================
// Problem constants
// ============================================================================
#define M_DIM 8192
#define N_DIM 4096
#define K_DIM 4096
#define BM 128
#define BN 256
#define BK 128
#define STAGES 4
#define NTHREADS 512
#define KIT (K_DIM / BK)  // 32

// Stage = A tile [128 rows][128 B] + B tile [256 rows][128 B]
#define A_TILE_BYTES (BM * BK)                      // 16384
#define B_TILE_BYTES (BN * BK)                      // 32768
#define STAGE_BYTES  (A_TILE_BYTES + B_TILE_BYTES)  // 49152
#define SOFF_FULL 0
#define SOFF_TILE 1024
#define SMEM_TOTAL (SOFF_TILE + STAGES * STAGE_BYTES)  // 197632

// fp8 scratch (device globals: allocation-free contract)
__device__ __align__(1024) unsigned char g_qx[(size_t)M_DIM * K_DIM];
__device__ __align__(1024) unsigned char g_qw[(size_t)N_DIM * K_DIM];

// ============================================================================
// PTX helpers (baseline sm_90/sm_89 features only — NO tcgen05)
// ============================================================================
__device__ __forceinline__ uint32_t smem_u32(const void* p) {
    uint32_t a;
    asm("{ .reg .u64 t; cvta.to.shared.u64 t, %1; cvt.u32.u64 %0, t; }"
        : "=r"(a) : "l"(p));
    return a;
}

#define MBARRIER_INIT(addr, count) \
    asm volatile("mbarrier.init.shared.b64 [%0], %1;" \
                 :: "r"((uint32_t)(addr)), "r"((uint32_t)(count)) : "memory")

#define MBARRIER_EXPECT_TX(addr, bytes) \
    asm volatile("mbarrier.arrive.expect_tx.shared.b64 _, [%0], %1;" \
                 :: "r"((uint32_t)(addr)), "r"((uint32_t)(bytes)) : "memory")

#define MBARRIER_WAIT_PARITY(addr, parity) do { \
    uint32_t _m = (uint32_t)(addr); uint32_t _p = (uint32_t)(parity); uint32_t _d; \
    asm volatile("{\n\t.reg .pred p;\n\t" \
        "mbarrier.try_wait.parity.acquire.cta.shared::cta.b64 p, [%1], %2;\n\t" \
        "selp.b32 %0, 1, 0, p;\n\t}" : "=r"(_d) : "r"(_m), "r"(_p) : "memory"); \
    if (!_d) { \
        asm volatile("{\n\t.reg .pred P1;\n\t" \
            "WL_%=:\n\t" \
            "mbarrier.try_wait.parity.acquire.cta.shared::cta.b64 P1, [%0], %1, 0x989680;\n\t" \
            "@P1 bra.uni WD_%=;\n\t" \
            "bra.uni WL_%=;\n\t" \
            "WD_%=:\n\t}" :: "r"(_m), "r"(_p) : "memory"); \
    } \
} while (0)

#define TMA_LOAD_2D(smem_addr, tmap_ptr, cx, cy, mbar) \
    asm volatile( \
        "cp.async.bulk.tensor.2d.shared::cta.global.tile.mbarrier::complete_tx::bytes " \
        "[%0], [%1, {%2, %3}], [%4];" \
        :: "r"((uint32_t)(smem_addr)), "l"(tmap_ptr), \
           "r"((int32_t)(cx)), "r"((int32_t)(cy)), "r"((uint32_t)(mbar)) : "memory")

__device__ __forceinline__ uint32_t lds32(uint32_t a) {
    uint32_t v;
    asm volatile("ld.shared.b32 %0, [%1];" : "=r"(v) : "r"(a));
    return v;
}

// fp8 e4m3 x e4m3 -> f32 mma, in-place accumulate (sm_89+ baseline feature)
__device__ __forceinline__ void mma_e4m3(float* d, const uint32_t* a,
                                         const uint32_t* b) {
    asm volatile(
        "mma.sync.aligned.m16n8k32.row.col.f32.e4m3.e4m3.f32 "
        "{%0,%1,%2,%3}, {%4,%5,%6,%7}, {%8,%9}, {%0,%1,%2,%3};"
        : "+f"(d[0]), "+f"(d[1]), "+f"(d[2]), "+f"(d[3])
        : "r"(a[0]), "r"(a[1]), "r"(a[2]), "r"(a[3]), "r"(b[0]), "r"(b[1]));
}

// ============================================================================
// Kernel 1: fp32 -> fp8 e4m3 quantization (matches reference path: IEEE div
// by scale, saturating rn cast to e4m3 grid). Weight path: scale=1 (values
// already on the e4m3 grid; rn cast is exact). 4 independent loads/thread.
// ============================================================================
__global__ void quant_kernel(const float4* __restrict__ src,
                             uint32_t* __restrict__ dst,
                             int n4,
                             const float* __restrict__ scale) {
    const float s = scale ? __ldg(scale) : 1.0f;
    const int base = blockIdx.x * blockDim.x + threadIdx.x;
    const int stride = gridDim.x * blockDim.x;
    #pragma unroll
    for (int j = 0; j < 4; j++) {
        int i = base + j * stride;
        if (i >= n4) break;
        float4 v = src[i];
        float a = __fdiv_rn(v.x, s);
        float b = __fdiv_rn(v.y, s);
        float c = __fdiv_rn(v.z, s);
        float d = __fdiv_rn(v.w, s);
        uint16_t lo, hi;
        // cvt d, a, b: d[7:0]=cvt(b), d[15:8]=cvt(a) -> byte0 = element 0
        asm("cvt.rn.satfinite.e4m3x2.f32 %0, %1, %2;" : "=h"(lo) : "f"(b), "f"(a));
        asm("cvt.rn.satfinite.e4m3x2.f32 %0, %1, %2;" : "=h"(hi) : "f"(d), "f"(c));
        dst[i] = (uint32_t)lo | ((uint32_t)hi << 16);
    }
}

// ============================================================================
// Kernel 2: multistage fp8 mma.sync GEMM
//   out[128,256] tile = qx[128,K] @ qw[256,K]^T  (both K-major)
//   16 warps (2 M x 8 N), warp tile 64x32 -> 4 warps/SMSP for latency hiding
// ============================================================================
__device__ __forceinline__ void issue_stage(uint32_t sbase, int it, int m0,
                                            int n0, const CUtensorMap* tA,
                                            const CUtensorMap* tB) {
    int s = it % STAGES;
    uint32_t full = sbase + SOFF_FULL + 8 * s;
    MBARRIER_EXPECT_TX(full, STAGE_BYTES);
    uint32_t st = sbase + SOFF_TILE + s * STAGE_BYTES;
    int k0 = it * BK;
    TMA_LOAD_2D(st,                tA, k0, m0, full);
    TMA_LOAD_2D(st + A_TILE_BYTES, tB, k0, n0, full);
}

__global__ void __launch_bounds__(NTHREADS, 1)
fp8_gemm_kernel(const __grid_constant__ CUtensorMap tmA,
                const __grid_constant__ CUtensorMap tmB,
                const float* __restrict__ bias,
                const float* __restrict__ in_scale,
                const float* __restrict__ w_scale,
                float* __restrict__ out) {
    extern __shared__ __align__(1024) unsigned char smem[];
    const uint32_t sbase = smem_u32(smem);
    const int tid = threadIdx.x;
    const int wid = tid >> 5;
    const int lane = tid & 31;
    const int gid = lane >> 2;   // group id 0..7 (fragment row-in-8)
    const int tig = lane & 3;    // thread-in-group
    const int warp_m = (wid & 1) * 64;    // 2 warps along M
    const int warp_n = (wid >> 1) * 32;   // 8 warps along N
    const int m0 = blockIdx.y * BM;
    const int n0 = blockIdx.x * BN;

    if (tid == 0) {
        #pragma unroll
        for (int s = 0; s < STAGES; s++)
            MBARRIER_INIT(sbase + SOFF_FULL + 8 * s, 1);
    }
    __syncthreads();

    // Prologue: fill STAGES-1 stages
    if (tid == 0) {
        issue_stage(sbase, 0, m0, n0, &tmA, &tmB);
        issue_stage(sbase, 1, m0, n0, &tmA, &tmB);
        issue_stage(sbase, 2, m0, n0, &tmA, &tmB);
    }

    // SW128 swizzle term for our rows is ((row&7)<<4) = gid<<4, constant
    // per thread. co[s4][h] = (s4*32 + h*16 + tig*4) ^ (gid<<4).
    const uint32_t sx = (uint32_t)gid << 4;
    uint32_t co[4][2];
    #pragma unroll
    for (int s4 = 0; s4 < 4; s4++) {
        #pragma unroll
        for (int h = 0; h < 2; h++)
            co[s4][h] = ((uint32_t)(s4 * 32 + h * 16 + tig * 4)) ^ sx;
    }
    const uint32_t baseA0 = (uint32_t)(warp_m + gid) * 128;
    const uint32_t baseB0 = (uint32_t)(warp_n + gid) * 128 + A_TILE_BYTES;

    float acc[4][4][4];   // 64 f32 accumulators, direct mma accumulation
    #pragma unroll
    for (int i = 0; i < 4; i++)
        #pragma unroll
        for (int j = 0; j < 4; j++)
            #pragma unroll
            for (int q = 0; q < 4; q++) acc[i][j][q] = 0.f;

    int s = 0, ph = 0;
    for (int it = 0; it < KIT; ++it) {
        MBARRIER_WAIT_PARITY(sbase + SOFF_FULL + 8 * s, ph);
        if (tid == 0 && it + 3 < KIT)
            issue_stage(sbase, it + 3, m0, n0, &tmA, &tmB);

        const uint32_t stg = sbase + SOFF_TILE + (uint32_t)s * STAGE_BYTES;
        const uint32_t aBase = stg + baseA0;
        const uint32_t bBase = stg + baseB0;
        #pragma unroll
        for (int s4 = 0; s4 < 4; s4++) {  // 4 x K=32 per BK=128 stage
            uint32_t Af[4][4];
            #pragma unroll
            for (int fm = 0; fm < 4; fm++) {
                const uint32_t a0 = aBase + fm * 2048 + co[s4][0];
                const uint32_t a1 = aBase + fm * 2048 + co[s4][1];
                Af[fm][0] = lds32(a0);
                Af[fm][1] = lds32(a0 + 1024);
                Af[fm][2] = lds32(a1);
                Af[fm][3] = lds32(a1 + 1024);
            }
            uint32_t Bf[4][2];
            #pragma unroll
            for (int fn = 0; fn < 4; fn++) {
                const uint32_t b0 = bBase + fn * 1024;
                Bf[fn][0] = lds32(b0 + co[s4][0]);
                Bf[fn][1] = lds32(b0 + co[s4][1]);
            }
            #pragma unroll
            for (int fm = 0; fm < 4; fm++)
                #pragma unroll
                for (int fn = 0; fn < 4; fn++)
                    mma_e4m3(acc[fm][fn], Af[fm], Bf[fn]);
        }
        __syncthreads();  // all reads of stage s done; buffer reusable
        if (++s == STAGES) { s = 0; ph ^= 1; }
    }

    // Epilogue: scale + bias, float2 stores
    const float sc = __ldg(in_scale) * __ldg(w_scale);
    #pragma unroll
    for (int fm = 0; fm < 4; fm++) {
        const int r0 = m0 + warp_m + fm * 16 + gid;
        #pragma unroll
        for (int fn = 0; fn < 4; fn++) {
            const int col = n0 + warp_n + fn * 8 + 2 * tig;
            const float2 bv = *reinterpret_cast<const float2*>(bias + col);
            float2 o0, o1;
            o0.x = fmaf(acc[fm][fn][0], sc, bv.x);
            o0.y = fmaf(acc[fm][fn][1], sc, bv.y);
            o1.x = fmaf(acc[fm][fn][2], sc, bv.x);
            o1.y = fmaf(acc[fm][fn][3], sc, bv.y);
            *reinterpret_cast<float2*>(out + (size_t)r0 * N_DIM + col) = o0;
            *reinterpret_cast<float2*>(out + (size_t)(r0 + 8) * N_DIM + col) = o1;
        }
    }
}

// ============================================================================
// Host launch
// ============================================================================
typedef CUresult (CUDAAPI* PFN_encodeTiled)(
    CUtensorMap*, CUtensorMapDataType, cuuint32_t, void*,
    const cuuint64_t*, const cuuint64_t*, const cuuint32_t*, const cuuint32_t*,
    CUtensorMapInterleave, CUtensorMapSwizzle, CUtensorMapL2promotion,
    CUtensorMapFloatOOBfill);

extern "C" void kernel_launch(void* const* d_in, const int* in_sizes, int n_in,
                              void* d_out, int out_size) {
    const float* x      = (const float*)d_in[0];
    const float* w      = (const float*)d_in[1];
    const float* wscale = (const float*)d_in[2];
    const float* bias   = (const float*)d_in[3];
    const float* iscale = (const float*)d_in[4];
    float* out = (float*)d_out;
    (void)in_sizes; (void)n_in; (void)out_size;

    void* qx_p = nullptr; void* qw_p = nullptr;
    cudaGetSymbolAddress(&qx_p, g_qx);
    cudaGetSymbolAddress(&qw_p, g_qw);

    // --- quantize activations (/input_scale) and weights (exact re-cast) ---
    int n4x = M_DIM * K_DIM / 4;   // 8388608
    int n4w = N_DIM * K_DIM / 4;   // 4194304
    quant_kernel<<<n4x / (256 * 4), 256>>>(
        (const float4*)x, (uint32_t*)qx_p, n4x, iscale);
    quant_kernel<<<n4w / (256 * 4), 256>>>(
        (const float4*)w, (uint32_t*)qw_p, n4w, nullptr);

    // --- TMA descriptors (driver entry point via cudart; no -lcuda needed) ---
    PFN_encodeTiled encode = nullptr;
    cudaDriverEntryPointQueryResult qr;
    cudaGetDriverEntryPoint("cuTensorMapEncodeTiled", (void**)&encode,
                            cudaEnableDefault, &qr);

    CUtensorMap tmA, tmB;
    {
        cuuint64_t dims[2]    = {K_DIM, M_DIM};
        cuuint64_t strides[1] = {K_DIM};   // bytes (uint8 elems)
        cuuint32_t box[2]     = {BK, BM};  // 128B rows: SW128 limit
        cuuint32_t es[2]      = {1, 1};
        encode(&tmA, CU_TENSOR_MAP_DATA_TYPE_UINT8, 2, qx_p, dims, strides,
               box, es, CU_TENSOR_MAP_INTERLEAVE_NONE, CU_TENSOR_MAP_SWIZZLE_128B,
               CU_TENSOR_MAP_L2_PROMOTION_L2_128B, CU_TENSOR_MAP_FLOAT_OOB_FILL_NONE);
    }
    {
        cuuint64_t dims[2]    = {K_DIM, N_DIM};
        cuuint64_t strides[1] = {K_DIM};
        cuuint32_t box[2]     = {BK, BN};  // 128 x 256 box
        cuuint32_t es[2]      = {1, 1};
        encode(&tmB, CU_TENSOR_MAP_DATA_TYPE_UINT8, 2, qw_p, dims, strides,
               box, es, CU_TENSOR_MAP_INTERLEAVE_NONE, CU_TENSOR_MAP_SWIZZLE_128B,
               CU_TENSOR_MAP_L2_PROMOTION_L2_128B, CU_TENSOR_MAP_FLOAT_OOB_FILL_NONE);
    }

    cudaFuncSetAttribute(fp8_gemm_kernel,
                         cudaFuncAttributeMaxDynamicSharedMemorySize, SMEM_TOTAL);
    dim3 grid(N_DIM / BN, M_DIM / BM);  // (16, 64) = 1024 CTAs
    fp8_gemm_kernel<<<grid, NTHREADS, SMEM_TOTAL>>>(
        tmA, tmB, bias, iscale, wscale, out);
}

// round 5
// speedup vs baseline: 1.0496x; 1.0124x over previous
#include <cuda_runtime.h>
#include <cuda.h>
#include <cstdint>

// ============================================================================
// Problem constants
// ============================================================================
#define M_DIM 8192
#define N_DIM 4096
#define K_DIM 4096
#define BM 128
#define BN 256
#define BK 128
#define STAGES 4
#define NTHREADS 512
#define KIT (K_DIM / BK)  // 32

// Stage = A tile [128 rows][128 B] + B tile [256 rows][128 B]
#define A_TILE_BYTES (BM * BK)                      // 16384
#define B_TILE_BYTES (BN * BK)                      // 32768
#define STAGE_BYTES  (A_TILE_BYTES + B_TILE_BYTES)  // 49152
#define SOFF_FULL 0
#define SOFF_TILE 1024
#define SMEM_TOTAL (SOFF_TILE + STAGES * STAGE_BYTES)  // 197632

// Quant geometry: one fused kernel, 4 float4 per thread, 256 thr/block
#define QX_BLOCKS ((M_DIM * K_DIM / 4) / 1024)   // 8192
#define QW_BLOCKS ((N_DIM * K_DIM / 4) / 1024)   // 4096

// fp8 scratch (device globals: allocation-free contract)
__device__ __align__(1024) unsigned char g_qx[(size_t)M_DIM * K_DIM];
__device__ __align__(1024) unsigned char g_qw[(size_t)N_DIM * K_DIM];

// ============================================================================
// PTX helpers (baseline sm_90/sm_89 features only — NO tcgen05; the harness
// PTX target is compute_103 (no 'a'), which rejects arch-specific instrs)
// ============================================================================
__device__ __forceinline__ uint32_t smem_u32(const void* p) {
    uint32_t a;
    asm("{ .reg .u64 t; cvta.to.shared.u64 t, %1; cvt.u32.u64 %0, t; }"
        : "=r"(a) : "l"(p));
    return a;
}

#define MBARRIER_INIT(addr, count) \
    asm volatile("mbarrier.init.shared.b64 [%0], %1;" \
                 :: "r"((uint32_t)(addr)), "r"((uint32_t)(count)) : "memory")

#define MBARRIER_EXPECT_TX(addr, bytes) \
    asm volatile("mbarrier.arrive.expect_tx.shared.b64 _, [%0], %1;" \
                 :: "r"((uint32_t)(addr)), "r"((uint32_t)(bytes)) : "memory")

#define MBARRIER_WAIT_PARITY(addr, parity) do { \
    uint32_t _m = (uint32_t)(addr); uint32_t _p = (uint32_t)(parity); uint32_t _d; \
    asm volatile("{\n\t.reg .pred p;\n\t" \
        "mbarrier.try_wait.parity.acquire.cta.shared::cta.b64 p, [%1], %2;\n\t" \
        "selp.b32 %0, 1, 0, p;\n\t}" : "=r"(_d) : "r"(_m), "r"(_p) : "memory"); \
    if (!_d) { \
        asm volatile("{\n\t.reg .pred P1;\n\t" \
            "WL_%=:\n\t" \
            "mbarrier.try_wait.parity.acquire.cta.shared::cta.b64 P1, [%0], %1, 0x989680;\n\t" \
            "@P1 bra.uni WD_%=;\n\t" \
            "bra.uni WL_%=;\n\t" \
            "WD_%=:\n\t}" :: "r"(_m), "r"(_p) : "memory"); \
    } \
} while (0)

#define TMA_LOAD_2D(smem_addr, tmap_ptr, cx, cy, mbar) \
    asm volatile( \
        "cp.async.bulk.tensor.2d.shared::cta.global.tile.mbarrier::complete_tx::bytes " \
        "[%0], [%1, {%2, %3}], [%4];" \
        :: "r"((uint32_t)(smem_addr)), "l"(tmap_ptr), \
           "r"((int32_t)(cx)), "r"((int32_t)(cy)), "r"((uint32_t)(mbar)) : "memory")

__device__ __forceinline__ uint32_t lds32(uint32_t a) {
    uint32_t v;
    asm volatile("ld.shared.b32 %0, [%1];" : "=r"(v) : "r"(a));
    return v;
}

// fp8 e4m3 x e4m3 -> f32 mma, in-place accumulate (sm_89+ baseline feature)
__device__ __forceinline__ void mma_e4m3(float* d, const uint32_t* a,
                                         const uint32_t* b) {
    asm volatile(
        "mma.sync.aligned.m16n8k32.row.col.f32.e4m3.e4m3.f32 "
        "{%0,%1,%2,%3}, {%4,%5,%6,%7}, {%8,%9}, {%0,%1,%2,%3};"
        : "+f"(d[0]), "+f"(d[1]), "+f"(d[2]), "+f"(d[3])
        : "r"(a[0]), "r"(a[1]), "r"(a[2]), "r"(a[3]), "r"(b[0]), "r"(b[1]));
}

// ============================================================================
// Kernel 1: fused fp32 -> fp8 e4m3 quantization for BOTH tensors.
//   Blocks [0, QX_BLOCKS): x / input_scale -> saturating rn e4m3 (matches
//     reference quantize path bit-exactly: IEEE f32 div, cvt.rn.satfinite).
//   Blocks [QX_BLOCKS, ..): weight, already on the e4m3 grid -> exact re-cast
//     (division by 1.0 skipped: exact identity).
//   4 consecutive-chunk float4 loads per thread, NO bounds guard (sizes are
//   exact multiples) -> front-batched LDG.128, MLP=4.
// ============================================================================
__global__ void __launch_bounds__(256) quant_fused_kernel(
        const float4* __restrict__ x,
        const float4* __restrict__ w,
        uint32_t* __restrict__ qx,
        uint32_t* __restrict__ qw,
        const float* __restrict__ in_scale) {
    const int b = blockIdx.x;
    const bool is_x = (b < QX_BLOCKS);
    const float4* __restrict__ src = is_x ? x : w;
    uint32_t* __restrict__ dst = is_x ? qx : qw;
    const int base = (is_x ? b : (b - QX_BLOCKS)) * 1024 + threadIdx.x;
    const float s = is_x ? __ldg(in_scale) : 1.0f;

    float4 v[4];
    #pragma unroll
    for (int j = 0; j < 4; j++) v[j] = src[base + j * 256];  // MLP=4

    #pragma unroll
    for (int j = 0; j < 4; j++) {
        float a, bb, c, d;
        if (is_x) {
            a  = __fdiv_rn(v[j].x, s);
            bb = __fdiv_rn(v[j].y, s);
            c  = __fdiv_rn(v[j].z, s);
            d  = __fdiv_rn(v[j].w, s);
        } else {  // scale == 1.0 -> division is exact identity
            a = v[j].x; bb = v[j].y; c = v[j].z; d = v[j].w;
        }
        uint16_t lo, hi;
        // cvt d, a, b: d[7:0]=cvt(b), d[15:8]=cvt(a) -> byte0 = element 0
        asm("cvt.rn.satfinite.e4m3x2.f32 %0, %1, %2;" : "=h"(lo) : "f"(bb), "f"(a));
        asm("cvt.rn.satfinite.e4m3x2.f32 %0, %1, %2;" : "=h"(hi) : "f"(d),  "f"(c));
        dst[base + j * 256] = (uint32_t)lo | ((uint32_t)hi << 16);
    }
}

// ============================================================================
// Kernel 2: multistage fp8 mma.sync GEMM (at the legacy-QMMA pipe floor:
//   rt_SMSP=24 for m16n8k32 -> 683 MACs/cyc/SM; measured 99.4% of it)
//   out[128,256] tile = qx[128,K] @ qw[256,K]^T  (both K-major)
//   16 warps (2 M x 8 N), warp tile 64x32; 4-stage TMA pipeline; SW128
// ============================================================================
__device__ __forceinline__ void issue_stage(uint32_t sbase, int it, int m0,
                                            int n0, const CUtensorMap* tA,
                                            const CUtensorMap* tB) {
    int s = it % STAGES;
    uint32_t full = sbase + SOFF_FULL + 8 * s;
    MBARRIER_EXPECT_TX(full, STAGE_BYTES);
    uint32_t st = sbase + SOFF_TILE + s * STAGE_BYTES;
    int k0 = it * BK;
    TMA_LOAD_2D(st,                tA, k0, m0, full);
    TMA_LOAD_2D(st + A_TILE_BYTES, tB, k0, n0, full);
}

__global__ void __launch_bounds__(NTHREADS, 1)
fp8_gemm_kernel(const __grid_constant__ CUtensorMap tmA,
                const __grid_constant__ CUtensorMap tmB,
                const float* __restrict__ bias,
                const float* __restrict__ in_scale,
                const float* __restrict__ w_scale,
                float* __restrict__ out) {
    extern __shared__ __align__(1024) unsigned char smem[];
    const uint32_t sbase = smem_u32(smem);
    const int tid = threadIdx.x;
    const int wid = tid >> 5;
    const int lane = tid & 31;
    const int gid = lane >> 2;   // group id 0..7 (fragment row-in-8)
    const int tig = lane & 3;    // thread-in-group
    const int warp_m = (wid & 1) * 64;    // 2 warps along M
    const int warp_n = (wid >> 1) * 32;   // 8 warps along N
    const int m0 = blockIdx.y * BM;
    const int n0 = blockIdx.x * BN;

    if (tid == 0) {
        #pragma unroll
        for (int s = 0; s < STAGES; s++)
            MBARRIER_INIT(sbase + SOFF_FULL + 8 * s, 1);
    }
    __syncthreads();

    // Prologue: fill STAGES-1 stages
    if (tid == 0) {
        issue_stage(sbase, 0, m0, n0, &tmA, &tmB);
        issue_stage(sbase, 1, m0, n0, &tmA, &tmB);
        issue_stage(sbase, 2, m0, n0, &tmA, &tmB);
    }

    // SW128 swizzle term for our rows is ((row&7)<<4) = gid<<4, constant
    // per thread. co[s4][h] = (s4*32 + h*16 + tig*4) ^ (gid<<4).
    const uint32_t sx = (uint32_t)gid << 4;
    uint32_t co[4][2];
    #pragma unroll
    for (int s4 = 0; s4 < 4; s4++) {
        #pragma unroll
        for (int h = 0; h < 2; h++)
            co[s4][h] = ((uint32_t)(s4 * 32 + h * 16 + tig * 4)) ^ sx;
    }
    const uint32_t baseA0 = (uint32_t)(warp_m + gid) * 128;
    const uint32_t baseB0 = (uint32_t)(warp_n + gid) * 128 + A_TILE_BYTES;

    float acc[4][4][4];   // 64 f32 accumulators, direct mma accumulation
    #pragma unroll
    for (int i = 0; i < 4; i++)
        #pragma unroll
        for (int j = 0; j < 4; j++)
            #pragma unroll
            for (int q = 0; q < 4; q++) acc[i][j][q] = 0.f;

    int s = 0, ph = 0;
    for (int it = 0; it < KIT; ++it) {
        MBARRIER_WAIT_PARITY(sbase + SOFF_FULL + 8 * s, ph);
        if (tid == 0 && it + 3 < KIT)
            issue_stage(sbase, it + 3, m0, n0, &tmA, &tmB);

        const uint32_t stg = sbase + SOFF_TILE + (uint32_t)s * STAGE_BYTES;
        const uint32_t aBase = stg + baseA0;
        const uint32_t bBase = stg + baseB0;
        #pragma unroll
        for (int s4 = 0; s4 < 4; s4++) {  // 4 x K=32 per BK=128 stage
            uint32_t Af[4][4];
            #pragma unroll
            for (int fm = 0; fm < 4; fm++) {
                const uint32_t a0 = aBase + fm * 2048 + co[s4][0];
                const uint32_t a1 = aBase + fm * 2048 + co[s4][1];
                Af[fm][0] = lds32(a0);
                Af[fm][1] = lds32(a0 + 1024);
                Af[fm][2] = lds32(a1);
                Af[fm][3] = lds32(a1 + 1024);
            }
            uint32_t Bf[4][2];
            #pragma unroll
            for (int fn = 0; fn < 4; fn++) {
                const uint32_t b0 = bBase + fn * 1024;
                Bf[fn][0] = lds32(b0 + co[s4][0]);
                Bf[fn][1] = lds32(b0 + co[s4][1]);
            }
            #pragma unroll
            for (int fm = 0; fm < 4; fm++)
                #pragma unroll
                for (int fn = 0; fn < 4; fn++)
                    mma_e4m3(acc[fm][fn], Af[fm], Bf[fn]);
        }
        __syncthreads();  // all reads of stage s done; buffer reusable
        if (++s == STAGES) { s = 0; ph ^= 1; }
    }

    // Epilogue: scale + bias, float2 stores
    const float sc = __ldg(in_scale) * __ldg(w_scale);
    #pragma unroll
    for (int fm = 0; fm < 4; fm++) {
        const int r0 = m0 + warp_m + fm * 16 + gid;
        #pragma unroll
        for (int fn = 0; fn < 4; fn++) {
            const int col = n0 + warp_n + fn * 8 + 2 * tig;
            const float2 bv = *reinterpret_cast<const float2*>(bias + col);
            float2 o0, o1;
            o0.x = fmaf(acc[fm][fn][0], sc, bv.x);
            o0.y = fmaf(acc[fm][fn][1], sc, bv.y);
            o1.x = fmaf(acc[fm][fn][2], sc, bv.x);
            o1.y = fmaf(acc[fm][fn][3], sc, bv.y);
            *reinterpret_cast<float2*>(out + (size_t)r0 * N_DIM + col) = o0;
            *reinterpret_cast<float2*>(out + (size_t)(r0 + 8) * N_DIM + col) = o1;
        }
    }
}

// ============================================================================
// Host launch
// ============================================================================
typedef CUresult (CUDAAPI* PFN_encodeTiled)(
    CUtensorMap*, CUtensorMapDataType, cuuint32_t, void*,
    const cuuint64_t*, const cuuint64_t*, const cuuint32_t*, const cuuint32_t*,
    CUtensorMapInterleave, CUtensorMapSwizzle, CUtensorMapL2promotion,
    CUtensorMapFloatOOBfill);

extern "C" void kernel_launch(void* const* d_in, const int* in_sizes, int n_in,
                              void* d_out, int out_size) {
    const float* x      = (const float*)d_in[0];
    const float* w      = (const float*)d_in[1];
    const float* wscale = (const float*)d_in[2];
    const float* bias   = (const float*)d_in[3];
    const float* iscale = (const float*)d_in[4];
    float* out = (float*)d_out;
    (void)in_sizes; (void)n_in; (void)out_size;

    void* qx_p = nullptr; void* qw_p = nullptr;
    cudaGetSymbolAddress(&qx_p, g_qx);
    cudaGetSymbolAddress(&qw_p, g_qw);

    // --- fused quantization: activations (/input_scale) + weights (re-cast) ---
    quant_fused_kernel<<<QX_BLOCKS + QW_BLOCKS, 256>>>(
        (const float4*)x, (const float4*)w,
        (uint32_t*)qx_p, (uint32_t*)qw_p, iscale);

    // --- TMA descriptors (driver entry point via cudart; no -lcuda needed) ---
    PFN_encodeTiled encode = nullptr;
    cudaDriverEntryPointQueryResult qr;
    cudaGetDriverEntryPoint("cuTensorMapEncodeTiled", (void**)&encode,
                            cudaEnableDefault, &qr);

    CUtensorMap tmA, tmB;
    {
        cuuint64_t dims[2]    = {K_DIM, M_DIM};
        cuuint64_t strides[1] = {K_DIM};   // bytes (uint8 elems)
        cuuint32_t box[2]     = {BK, BM};  // 128B rows: SW128 limit
        cuuint32_t es[2]      = {1, 1};
        encode(&tmA, CU_TENSOR_MAP_DATA_TYPE_UINT8, 2, qx_p, dims, strides,
               box, es, CU_TENSOR_MAP_INTERLEAVE_NONE, CU_TENSOR_MAP_SWIZZLE_128B,
               CU_TENSOR_MAP_L2_PROMOTION_L2_128B, CU_TENSOR_MAP_FLOAT_OOB_FILL_NONE);
    }
    {
        cuuint64_t dims[2]    = {K_DIM, N_DIM};
        cuuint64_t strides[1] = {K_DIM};
        cuuint32_t box[2]     = {BK, BN};  // 128 x 256 box
        cuuint32_t es[2]      = {1, 1};
        encode(&tmB, CU_TENSOR_MAP_DATA_TYPE_UINT8, 2, qw_p, dims, strides,
               box, es, CU_TENSOR_MAP_INTERLEAVE_NONE, CU_TENSOR_MAP_SWIZZLE_128B,
               CU_TENSOR_MAP_L2_PROMOTION_L2_128B, CU_TENSOR_MAP_FLOAT_OOB_FILL_NONE);
    }

    cudaFuncSetAttribute(fp8_gemm_kernel,
                         cudaFuncAttributeMaxDynamicSharedMemorySize, SMEM_TOTAL);
    dim3 grid(N_DIM / BN, M_DIM / BM);  // (16, 64) = 1024 CTAs
    fp8_gemm_kernel<<<grid, NTHREADS, SMEM_TOTAL>>>(
        tmA, tmB, bias, iscale, wscale, out);
}

// round 6
// speedup vs baseline: 1.2598x; 1.2003x over previous
#include <cuda_runtime.h>
#include <cuda.h>
#include <cstdint>

// ============================================================================
// Problem constants
// ============================================================================
#define M_DIM 8192
#define N_DIM 4096
#define K_DIM 4096
#define BM 128
#define BN 128
#define BK 128            // in f16 elements
#define STAGES 3
#define NTHREADS 256
#define KIT (K_DIM / BK)  // 32

// Stage = A [2 chunks][128 rows][128 B] + B [2 chunks][128 rows][128 B]
// (chunk = 64 f16 of K = 128 bytes per row; SW128 box limit)
#define CHUNK_BYTES 16384
#define A_TILE_BYTES (2 * CHUNK_BYTES)   // 32768
#define STAGE_BYTES  (4 * CHUNK_BYTES)   // 65536
#define SOFF_FULL 0
#define SOFF_TILE 1024
#define SMEM_TOTAL (SOFF_TILE + STAGES * STAGE_BYTES)  // 197632

// Quant geometry: fused kernel, 4 float4 per thread, 256 thr/block
#define QX_BLOCKS ((M_DIM * K_DIM / 4) / 1024)   // 8192
#define QW_BLOCKS ((N_DIM * K_DIM / 4) / 1024)   // 4096

// f16 scratch (device globals: allocation-free contract); stored as u32 pairs
__device__ __align__(1024) uint32_t g_qx[(size_t)M_DIM * K_DIM / 2];
__device__ __align__(1024) uint32_t g_qw[(size_t)N_DIM * K_DIM / 2];

// ============================================================================
// PTX helpers (baseline sm_90/sm_89 features only — NO tcgen05; harness PTX
// target is compute_103 (no 'a'), which rejects arch-specific instructions)
// ============================================================================
__device__ __forceinline__ uint32_t smem_u32(const void* p) {
    uint32_t a;
    asm("{ .reg .u64 t; cvta.to.shared.u64 t, %1; cvt.u32.u64 %0, t; }"
        : "=r"(a) : "l"(p));
    return a;
}

#define MBARRIER_INIT(addr, count) \
    asm volatile("mbarrier.init.shared.b64 [%0], %1;" \
                 :: "r"((uint32_t)(addr)), "r"((uint32_t)(count)) : "memory")

#define MBARRIER_EXPECT_TX(addr, bytes) \
    asm volatile("mbarrier.arrive.expect_tx.shared.b64 _, [%0], %1;" \
                 :: "r"((uint32_t)(addr)), "r"((uint32_t)(bytes)) : "memory")

#define MBARRIER_WAIT_PARITY(addr, parity) do { \
    uint32_t _m = (uint32_t)(addr); uint32_t _p = (uint32_t)(parity); uint32_t _d; \
    asm volatile("{\n\t.reg .pred p;\n\t" \
        "mbarrier.try_wait.parity.acquire.cta.shared::cta.b64 p, [%1], %2;\n\t" \
        "selp.b32 %0, 1, 0, p;\n\t}" : "=r"(_d) : "r"(_m), "r"(_p) : "memory"); \
    if (!_d) { \
        asm volatile("{\n\t.reg .pred P1;\n\t" \
            "WL_%=:\n\t" \
            "mbarrier.try_wait.parity.acquire.cta.shared::cta.b64 P1, [%0], %1, 0x989680;\n\t" \
            "@P1 bra.uni WD_%=;\n\t" \
            "bra.uni WL_%=;\n\t" \
            "WD_%=:\n\t}" :: "r"(_m), "r"(_p) : "memory"); \
    } \
} while (0)

#define TMA_LOAD_2D(smem_addr, tmap_ptr, cx, cy, mbar) \
    asm volatile( \
        "cp.async.bulk.tensor.2d.shared::cta.global.tile.mbarrier::complete_tx::bytes " \
        "[%0], [%1, {%2, %3}], [%4];" \
        :: "r"((uint32_t)(smem_addr)), "l"(tmap_ptr), \
           "r"((int32_t)(cx)), "r"((int32_t)(cy)), "r"((uint32_t)(mbar)) : "memory")

__device__ __forceinline__ uint32_t lds32(uint32_t a) {
    uint32_t v;
    asm volatile("ld.shared.b32 %0, [%1];" : "=r"(v) : "r"(a));
    return v;
}

// f16 x f16 -> f32 mma, in-place accumulate. Byte-level fragment layout is
// IDENTICAL to the fp8 m16n8k32 fragments (4B at byte 4*tig and 16+4*tig,
// rows gid / gid+8), so fp8 addressing carries over unchanged.
__device__ __forceinline__ void mma_f16(float* d, const uint32_t* a,
                                        const uint32_t* b) {
    asm volatile(
        "mma.sync.aligned.m16n8k16.row.col.f32.f16.f16.f32 "
        "{%0,%1,%2,%3}, {%4,%5,%6,%7}, {%8,%9}, {%0,%1,%2,%3};"
        : "+f"(d[0]), "+f"(d[1]), "+f"(d[2]), "+f"(d[3])
        : "r"(a[0]), "r"(a[1]), "r"(a[2]), "r"(a[3]), "r"(b[0]), "r"(b[1]));
}

// ============================================================================
// Kernel 1: fused quantization for BOTH tensors -> f16 values ON the e4m3 grid.
//   Path matches reference bit-exactly: IEEE f32 div by scale, saturating rn
//   cast to e4m3 (the quantization), then EXACT e4m3 -> f16 widening.
//   Weight blocks skip the division (scale 1.0, already on grid).
//   4 consecutive float4 loads per thread, no guard -> MLP=4.
// ============================================================================
__global__ void __launch_bounds__(256) quant_fused_kernel(
        const float4* __restrict__ x,
        const float4* __restrict__ w,
        uint32_t* __restrict__ qx,
        uint32_t* __restrict__ qw,
        const float* __restrict__ in_scale) {
    const int b = blockIdx.x;
    const bool is_x = (b < QX_BLOCKS);
    const float4* __restrict__ src = is_x ? x : w;
    uint32_t* __restrict__ dst = is_x ? qx : qw;
    const int base = (is_x ? b : (b - QX_BLOCKS)) * 1024 + threadIdx.x;
    const float s = is_x ? __ldg(in_scale) : 1.0f;

    float4 v[4];
    #pragma unroll
    for (int j = 0; j < 4; j++) v[j] = src[base + j * 256];  // MLP=4

    #pragma unroll
    for (int j = 0; j < 4; j++) {
        float a, bb, c, d;
        if (is_x) {
            a  = __fdiv_rn(v[j].x, s);
            bb = __fdiv_rn(v[j].y, s);
            c  = __fdiv_rn(v[j].z, s);
            d  = __fdiv_rn(v[j].w, s);
        } else {  // scale == 1.0 -> identity
            a = v[j].x; bb = v[j].y; c = v[j].z; d = v[j].w;
        }
        uint16_t lo8, hi8;
        // cvt d, a, b: d[7:0]=cvt(b), d[15:8]=cvt(a) -> byte0 = element 0
        asm("cvt.rn.satfinite.e4m3x2.f32 %0, %1, %2;" : "=h"(lo8) : "f"(bb), "f"(a));
        asm("cvt.rn.satfinite.e4m3x2.f32 %0, %1, %2;" : "=h"(hi8) : "f"(d),  "f"(c));
        uint32_t lo16, hi16;  // exact widening e4m3 -> f16 (half0 = byte0)
        asm("cvt.rn.f16x2.e4m3x2 %0, %1;" : "=r"(lo16) : "h"(lo8));
        asm("cvt.rn.f16x2.e4m3x2 %0, %1;" : "=r"(hi16) : "h"(hi8));
        uint2 o; o.x = lo16; o.y = hi16;
        *reinterpret_cast<uint2*>(dst + 2 * (base + j * 256)) = o;
    }
}

// ============================================================================
// Kernel 2: multistage f16 mma.sync GEMM (instruction-class experiment vs the
//   fp8 QMMA dispatch floor measured at ~24 cyc/SMSP)
//   out[128,128] tile = qx[128,K] @ qw[128,K]^T  (both K-major f16)
//   8 warps (2 M x 4 N), warp tile 64x32; 3-stage TMA pipeline; SW128
// ============================================================================
__device__ __forceinline__ void issue_stage(uint32_t sbase, int it, int m0,
                                            int n0, const CUtensorMap* tA,
                                            const CUtensorMap* tB) {
    int s = it % STAGES;
    uint32_t full = sbase + SOFF_FULL + 8 * s;
    MBARRIER_EXPECT_TX(full, STAGE_BYTES);
    uint32_t st = sbase + SOFF_TILE + s * STAGE_BYTES;
    int k0 = it * BK;  // element coords
    TMA_LOAD_2D(st,                   tA, k0,      m0, full);
    TMA_LOAD_2D(st + CHUNK_BYTES,     tA, k0 + 64, m0, full);
    TMA_LOAD_2D(st + 2 * CHUNK_BYTES, tB, k0,      n0, full);
    TMA_LOAD_2D(st + 3 * CHUNK_BYTES, tB, k0 + 64, n0, full);
}

__global__ void __launch_bounds__(NTHREADS, 1)
f16_gemm_kernel(const __grid_constant__ CUtensorMap tmA,
                const __grid_constant__ CUtensorMap tmB,
                const float* __restrict__ bias,
                const float* __restrict__ in_scale,
                const float* __restrict__ w_scale,
                float* __restrict__ out) {
    extern __shared__ __align__(1024) unsigned char smem[];
    const uint32_t sbase = smem_u32(smem);
    const int tid = threadIdx.x;
    const int wid = tid >> 5;
    const int lane = tid & 31;
    const int gid = lane >> 2;   // group id 0..7 (fragment row-in-8)
    const int tig = lane & 3;    // thread-in-group
    const int warp_m = (wid & 1) * 64;    // 2 warps along M
    const int warp_n = (wid >> 1) * 32;   // 4 warps along N
    const int m0 = blockIdx.y * BM;
    const int n0 = blockIdx.x * BN;

    if (tid == 0) {
        #pragma unroll
        for (int s = 0; s < STAGES; s++)
            MBARRIER_INIT(sbase + SOFF_FULL + 8 * s, 1);
    }
    __syncthreads();

    // Prologue: fill STAGES-1 stages
    if (tid == 0) {
        issue_stage(sbase, 0, m0, n0, &tmA, &tmB);
        issue_stage(sbase, 1, m0, n0, &tmA, &tmB);
    }

    // SW128 swizzle term for our rows is ((row&7)<<4) = gid<<4, constant per
    // thread. kstep byte offsets (32B per k16): co[s4][h] as in the fp8 kernel.
    const uint32_t sx = (uint32_t)gid << 4;
    uint32_t co[4][2];
    #pragma unroll
    for (int s4 = 0; s4 < 4; s4++) {
        #pragma unroll
        for (int h = 0; h < 2; h++)
            co[s4][h] = ((uint32_t)(s4 * 32 + h * 16 + tig * 4)) ^ sx;
    }
    const uint32_t baseA0 = (uint32_t)(warp_m + gid) * 128;
    const uint32_t baseB0 = (uint32_t)(warp_n + gid) * 128 + A_TILE_BYTES;

    float acc[4][4][4];   // 64 f32 accumulators, direct mma accumulation
    #pragma unroll
    for (int i = 0; i < 4; i++)
        #pragma unroll
        for (int j = 0; j < 4; j++)
            #pragma unroll
            for (int q = 0; q < 4; q++) acc[i][j][q] = 0.f;

    int s = 0, ph = 0;
    for (int it = 0; it < KIT; ++it) {
        MBARRIER_WAIT_PARITY(sbase + SOFF_FULL + 8 * s, ph);
        if (tid == 0 && it + 2 < KIT)
            issue_stage(sbase, it + 2, m0, n0, &tmA, &tmB);

        const uint32_t stg = sbase + SOFF_TILE + (uint32_t)s * STAGE_BYTES;
        #pragma unroll
        for (int ck = 0; ck < 2; ck++) {  // 2 chunks of 64 k-elems
            const uint32_t aBase = stg + ck * CHUNK_BYTES + baseA0;
            const uint32_t bBase = stg + ck * CHUNK_BYTES + baseB0;
            #pragma unroll
            for (int s4 = 0; s4 < 4; s4++) {  // 4 x k16 per chunk
                uint32_t Af[4][4];
                #pragma unroll
                for (int fm = 0; fm < 4; fm++) {
                    const uint32_t a0 = aBase + fm * 2048 + co[s4][0];
                    const uint32_t a1 = aBase + fm * 2048 + co[s4][1];
                    Af[fm][0] = lds32(a0);
                    Af[fm][1] = lds32(a0 + 1024);
                    Af[fm][2] = lds32(a1);
                    Af[fm][3] = lds32(a1 + 1024);
                }
                uint32_t Bf[4][2];
                #pragma unroll
                for (int fn = 0; fn < 4; fn++) {
                    const uint32_t b0 = bBase + fn * 1024;
                    Bf[fn][0] = lds32(b0 + co[s4][0]);
                    Bf[fn][1] = lds32(b0 + co[s4][1]);
                }
                #pragma unroll
                for (int fm = 0; fm < 4; fm++)
                    #pragma unroll
                    for (int fn = 0; fn < 4; fn++)
                        mma_f16(acc[fm][fn], Af[fm], Bf[fn]);
            }
        }
        __syncthreads();  // all reads of stage s done; buffer reusable
        if (++s == STAGES) { s = 0; ph ^= 1; }
    }

    // Epilogue: scale + bias, float2 stores
    const float sc = __ldg(in_scale) * __ldg(w_scale);
    #pragma unroll
    for (int fm = 0; fm < 4; fm++) {
        const int r0 = m0 + warp_m + fm * 16 + gid;
        #pragma unroll
        for (int fn = 0; fn < 4; fn++) {
            const int col = n0 + warp_n + fn * 8 + 2 * tig;
            const float2 bv = *reinterpret_cast<const float2*>(bias + col);
            float2 o0, o1;
            o0.x = fmaf(acc[fm][fn][0], sc, bv.x);
            o0.y = fmaf(acc[fm][fn][1], sc, bv.y);
            o1.x = fmaf(acc[fm][fn][2], sc, bv.x);
            o1.y = fmaf(acc[fm][fn][3], sc, bv.y);
            *reinterpret_cast<float2*>(out + (size_t)r0 * N_DIM + col) = o0;
            *reinterpret_cast<float2*>(out + (size_t)(r0 + 8) * N_DIM + col) = o1;
        }
    }
}

// ============================================================================
// Host launch
// ============================================================================
typedef CUresult (CUDAAPI* PFN_encodeTiled)(
    CUtensorMap*, CUtensorMapDataType, cuuint32_t, void*,
    const cuuint64_t*, const cuuint64_t*, const cuuint32_t*, const cuuint32_t*,
    CUtensorMapInterleave, CUtensorMapSwizzle, CUtensorMapL2promotion,
    CUtensorMapFloatOOBfill);

extern "C" void kernel_launch(void* const* d_in, const int* in_sizes, int n_in,
                              void* d_out, int out_size) {
    const float* x      = (const float*)d_in[0];
    const float* w      = (const float*)d_in[1];
    const float* wscale = (const float*)d_in[2];
    const float* bias   = (const float*)d_in[3];
    const float* iscale = (const float*)d_in[4];
    float* out = (float*)d_out;
    (void)in_sizes; (void)n_in; (void)out_size;

    void* qx_p = nullptr; void* qw_p = nullptr;
    cudaGetSymbolAddress(&qx_p, g_qx);
    cudaGetSymbolAddress(&qw_p, g_qw);

    // --- fused quantization to f16-on-e4m3-grid ---
    quant_fused_kernel<<<QX_BLOCKS + QW_BLOCKS, 256>>>(
        (const float4*)x, (const float4*)w,
        (uint32_t*)qx_p, (uint32_t*)qw_p, iscale);

    // --- TMA descriptors (driver entry point via cudart; no -lcuda needed) ---
    PFN_encodeTiled encode = nullptr;
    cudaDriverEntryPointQueryResult qr;
    cudaGetDriverEntryPoint("cuTensorMapEncodeTiled", (void**)&encode,
                            cudaEnableDefault, &qr);

    CUtensorMap tmA, tmB;
    {
        cuuint64_t dims[2]    = {K_DIM, M_DIM};       // elems
        cuuint64_t strides[1] = {K_DIM * 2};          // bytes
        cuuint32_t box[2]     = {64, BM};             // 64 f16 = 128B (SW128)
        cuuint32_t es[2]      = {1, 1};
        encode(&tmA, CU_TENSOR_MAP_DATA_TYPE_FLOAT16, 2, qx_p, dims, strides,
               box, es, CU_TENSOR_MAP_INTERLEAVE_NONE, CU_TENSOR_MAP_SWIZZLE_128B,
               CU_TENSOR_MAP_L2_PROMOTION_L2_128B, CU_TENSOR_MAP_FLOAT_OOB_FILL_NONE);
    }
    {
        cuuint64_t dims[2]    = {K_DIM, N_DIM};
        cuuint64_t strides[1] = {K_DIM * 2};
        cuuint32_t box[2]     = {64, BN};
        cuuint32_t es[2]      = {1, 1};
        encode(&tmB, CU_TENSOR_MAP_DATA_TYPE_FLOAT16, 2, qw_p, dims, strides,
               box, es, CU_TENSOR_MAP_INTERLEAVE_NONE, CU_TENSOR_MAP_SWIZZLE_128B,
               CU_TENSOR_MAP_L2_PROMOTION_L2_128B, CU_TENSOR_MAP_FLOAT_OOB_FILL_NONE);
    }

    cudaFuncSetAttribute(f16_gemm_kernel,
                         cudaFuncAttributeMaxDynamicSharedMemorySize, SMEM_TOTAL);
    dim3 grid(N_DIM / BN, M_DIM / BM);  // (32, 64) = 2048 CTAs
    f16_gemm_kernel<<<grid, NTHREADS, SMEM_TOTAL>>>(
        tmA, tmB, bias, iscale, wscale, out);
}